// round 16
// baseline (speedup 1.0000x reference)
#include <cuda_runtime.h>
#include <cstdint>

// CostVolume1D: out[n,d,h,w] = (1/C) * sum_c f1[n,c,h,w] * f2pad[n,c,h,w+d-4]
// f1,f2: [4,128,192,640] fp32. FINAL (R14 champion):
//  - One CTA per (n,h) row, TPB=160, launch_bounds(160,6): 768 CTAs <= 888
//    resident slots -> ALL CTAs resident from t=0, no straggler tail.
//  - 6-stage cp.async.bulk smem ring, per-stage mbarrier complete_tx;
//    thread 0 issues 2 bulk row copies per channel.
//  - Paired channels: 2 channels per iteration, one __syncthreads per pair,
//    refill issued right after the waits (before compute).
//  - Compute: 4 LDS.128 + 36 FFMA per thread per channel; f2 halo in smem.
// Measured: ncu 74.9us, DRAM 85.5% (6.78 TB/s), traffic = compulsory 508MB.

#define Nn     4
#define Cc     128
#define Hh     192
#define Ww     640
#define NS     9
#define TPB    160
#define VW     160                 // float4 per row
#define CH4    (Hh * VW)           // channel stride in float4 units (30720)
#define STAGES 6
#define ROWB   2560                // one row = 160 float4 = 2560 B
#define S1B    2560                // f1 region in slot
#define S2B    2592                // f2 region: 16B halo + 2560 + 16B halo
#define SLOTB  (S1B + S2B)         // 5152 B per stage

__device__ __forceinline__ uint32_t smem_u32(const void* p) {
    uint32_t a;
    asm("{ .reg .u64 t; cvta.to.shared.u64 t, %1; cvt.u32.u64 %0, t; }"
        : "=r"(a) : "l"(p));
    return a;
}
__device__ __forceinline__ void mbar_init(uint32_t m, uint32_t cnt) {
    asm volatile("mbarrier.init.shared.b64 [%0], %1;" :: "r"(m), "r"(cnt) : "memory");
}
__device__ __forceinline__ void mbar_expect(uint32_t m, uint32_t bytes) {
    asm volatile("mbarrier.arrive.expect_tx.shared.b64 _, [%0], %1;"
                 :: "r"(m), "r"(bytes) : "memory");
}
__device__ __forceinline__ void bulk_g2s(uint32_t dst, const void* src,
                                         uint32_t bytes, uint32_t m) {
    asm volatile("cp.async.bulk.shared::cta.global.mbarrier::complete_tx::bytes "
                 "[%0], [%1], %2, [%3];"
                 :: "r"(dst), "l"(src), "r"(bytes), "r"(m) : "memory");
}
__device__ __forceinline__ void mbar_wait(uint32_t m, uint32_t ph) {
    uint32_t done;
    asm volatile(
        "{\n\t.reg .pred p;\n\t"
        "mbarrier.try_wait.parity.acquire.cta.shared::cta.b64 p, [%1], %2;\n\t"
        "selp.b32 %0, 1, 0, p;\n\t}"
        : "=r"(done) : "r"(m), "r"(ph) : "memory");
    if (!done) {
        asm volatile(
            "{\n\t.reg .pred P1;\n\t"
            "WL_%=:\n\t"
            "mbarrier.try_wait.parity.acquire.cta.shared::cta.b64 P1, [%0], %1;\n\t"
            "@P1 bra.uni WD_%=;\n\t"
            "bra.uni WL_%=;\n\t"
            "WD_%=:\n\t}"
            :: "r"(m), "r"(ph) : "memory");
    }
}

__global__ __launch_bounds__(TPB, 6)
void costvol1d_kernel(const float4* __restrict__ f1,
                      const float4* __restrict__ f2,
                      float* __restrict__ out)
{
    __shared__ __align__(16) char buf[STAGES * SLOTB];
    __shared__ __align__(8)  uint64_t mbar[STAGES];

    const int tid = threadIdx.x;            // 0..159 == float4 index v
    const int bx  = blockIdx.x;             // n*Hh + h
    const int n   = bx / Hh;
    const int h   = bx % Hh;

    const uint32_t sbuf = smem_u32(buf);
    const uint32_t smb  = smem_u32(mbar);

    if (tid == 0) {
        #pragma unroll
        for (int s = 0; s < STAGES; s++) mbar_init(smb + s * 8, 1);
    }
    // Zero the 16B halos (front+back) of every stage's f2 region once.
    // Bulk copies only ever write [S1B+16, S1B+16+2560) within a slot.
    if (tid < STAGES * 2) {
        const int s    = tid >> 1;
        const int back = tid & 1;
        float4* p = (float4*)(buf + s * SLOTB + S1B + (back ? (S2B - 16) : 0));
        *p = make_float4(0.f, 0.f, 0.f, 0.f);
    }
    __syncthreads();   // barriers + halos visible before any bulk/consume

    // Row base (in float4 units); channel c row starts at rb + c*CH4.
    const size_t rb = ((size_t)n * Cc * Hh + h) * VW;

    // Prologue: channels 0..3 into stages 0..3 (channel c lives in stage c%6).
    if (tid == 0) {
        #pragma unroll
        for (int s = 0; s < 4; s++) {
            const uint32_t slot = sbuf + s * SLOTB;
            mbar_expect(smb + s * 8, 2 * ROWB);
            bulk_g2s(slot,             f1 + rb + (size_t)s * CH4, ROWB, smb + s * 8);
            bulk_g2s(slot + S1B + 16,  f2 + rb + (size_t)s * CH4, ROWB, smb + s * 8);
        }
    }

    float acc[NS * 4];
    #pragma unroll
    for (int i = 0; i < NS * 4; i++) acc[i] = 0.0f;

    int ss = 0;     // stage of channel c (c even; pair = stages ss, ss+1)
    int ph = 0;     // parity for this reuse round of the ring

    for (int c = 0; c < Cc; c += 2) {
        // Wait for the pair (channels c, c+1).
        mbar_wait(smb + ss * 8, ph);
        mbar_wait(smb + (ss + 1) * 8, ph);

        // Refill EARLY: channels c+4, c+5 into stages (ss+4)%6, (ss+5)%6.
        // Those stages held channels c-2, c-1, consumed last iteration and
        // protected by last iteration's __syncthreads (skew <= 1 iteration).
        if (tid == 0 && c + 4 < Cc) {
            const int s4 = (ss + 4 < STAGES) ? (ss + 4) : (ss - 2);
            const int s5 = (ss + 5 < STAGES) ? (ss + 5) : (ss - 1);
            const uint32_t w4 = sbuf + s4 * SLOTB;
            const uint32_t w5 = sbuf + s5 * SLOTB;
            mbar_expect(smb + s4 * 8, 2 * ROWB);
            bulk_g2s(w4,            f1 + rb + (size_t)(c + 4) * CH4, ROWB, smb + s4 * 8);
            bulk_g2s(w4 + S1B + 16, f2 + rb + (size_t)(c + 4) * CH4, ROWB, smb + s4 * 8);
            mbar_expect(smb + s5 * 8, 2 * ROWB);
            bulk_g2s(w5,            f1 + rb + (size_t)(c + 5) * CH4, ROWB, smb + s5 * 8);
            bulk_g2s(w5 + S1B + 16, f2 + rb + (size_t)(c + 5) * CH4, ROWB, smb + s5 * 8);
        }

        // Consume both channels of the pair.
        #pragma unroll
        for (int u = 0; u < 2; u++) {
            const char* slot = buf + (ss + u) * SLOTB;
            const float4* s1p = (const float4*)(slot);
            const float4* s2p = (const float4*)(slot + S1B);

            const float4 a  = s1p[tid];
            const float4 wa = s2p[tid];       // f2pad[4v-4 .. 4v-1]
            const float4 wb = s2p[tid + 1];   // f2pad[4v   .. 4v+3]
            const float4 wc = s2p[tid + 2];   // f2pad[4v+4 .. 4v+7]

            float win[12];
            win[0] = wa.x; win[1] = wa.y; win[2]  = wa.z; win[3]  = wa.w;
            win[4] = wb.x; win[5] = wb.y; win[6]  = wb.z; win[7]  = wb.w;
            win[8] = wc.x; win[9] = wc.y; win[10] = wc.z; win[11] = wc.w;

            float av[4];
            av[0] = a.x; av[1] = a.y; av[2] = a.z; av[3] = a.w;

            #pragma unroll
            for (int d = 0; d < NS; d++) {
                #pragma unroll
                for (int j = 0; j < 4; j++) {
                    acc[d * 4 + j] = fmaf(av[j], win[j + d], acc[d * 4 + j]);
                }
            }
        }

        __syncthreads();   // all threads done with this pair before it can be
                           // overwritten by the refill two channels from now.

        ss += 2;
        if (ss == STAGES) { ss = 0; ph ^= 1; }
    }

    // Epilogue: channel mean, float4 stores. out[n][d][h][4v .. 4v+3]
    const float inv = 1.0f / (float)Cc;
    float4* o4 = (float4*)out;
    #pragma unroll
    for (int d = 0; d < NS; d++) {
        float4 o;
        o.x = acc[d * 4 + 0] * inv;
        o.y = acc[d * 4 + 1] * inv;
        o.z = acc[d * 4 + 2] * inv;
        o.w = acc[d * 4 + 3] * inv;
        o4[((size_t)(n * NS + d) * Hh + h) * VW + tid] = o;
    }
}

extern "C" void kernel_launch(void* const* d_in, const int* in_sizes, int n_in,
                              void* d_out, int out_size)
{
    const float4* f1 = (const float4*)d_in[0];
    const float4* f2 = (const float4*)d_in[1];
    float* out = (float*)d_out;
    (void)in_sizes; (void)n_in; (void)out_size;

    dim3 grid(Nn * Hh);   // 768 CTAs, one per (n,h) row — all resident at occ 6
    dim3 block(TPB);      // 160 threads
    costvol1d_kernel<<<grid, block>>>(f1, f2, out);
}